// round 10
// baseline (speedup 1.0000x reference)
#include <cuda_runtime.h>
#include <cstdint>

// out[b][o][i][l] = white_table[o][i][ x[b][i][o][l] ]
// B=8, O=I=64, L=2048. L-axis contiguous in both input and output -> the
// channel "transpose" costs nothing: one block per (b,o,i) reads and writes
// fully-coalesced vec4 rows. 1KB per-(o,i) LUT in smem.
//
// FINAL FORM (measured best over 6 controlled variants): simple rolled
// 2-iteration vec4 stream, grid 4096 = one (o,i) pair per block, 8 batches
// looped inside. Sustains 6.36 TB/s (80.3% DRAM) — the practical HBM3e
// mixed read/write ceiling. MLP batching, cache hints, persistent grids,
// LUT replication, and startup prefetch were all tested and all neutral or
// worse: this kernel is memory-system-bound, not SM-bound.

#define B_DIM 8
#define CH 64
#define L_DIM 2048
#define THREADS 256

__global__ __launch_bounds__(THREADS) void white_transpose_kernel(
    const int* __restrict__ x,
    const float* __restrict__ table,
    float* __restrict__ out)
{
    const int idx = blockIdx.x;          // 0..4095
    const int i = idx & (CH - 1);
    const int o = idx >> 6;

    __shared__ float lut[256];
    lut[threadIdx.x] = table[((o * CH + i) << 8) + threadIdx.x];
    __syncthreads();

    const size_t bstride4 = (size_t)CH * CH * (L_DIM / 4);  // int4 units per batch
    const int4* __restrict__ xin =
        reinterpret_cast<const int4*>(x) + (size_t)(i * CH + o) * (L_DIM / 4);
    float4* __restrict__ op =
        reinterpret_cast<float4*>(out) + (size_t)(o * CH + i) * (L_DIM / 4);

    #pragma unroll
    for (int b = 0; b < B_DIM; b++) {
        const size_t base = b * bstride4;
        #pragma unroll
        for (int v = 0; v < (L_DIM / 4) / THREADS; v++) {
            const int vi = v * THREADS + threadIdx.x;
            int4 xi = xin[base + vi];
            float4 r;
            r.x = lut[xi.x];
            r.y = lut[xi.y];
            r.z = lut[xi.z];
            r.w = lut[xi.w];
            op[base + vi] = r;
        }
    }
}

extern "C" void kernel_launch(void* const* d_in, const int* in_sizes, int n_in,
                              void* d_out, int out_size)
{
    const int* x = (const int*)d_in[0];          // [8, 64, 64, 2048] int32
    const float* table = (const float*)d_in[1];  // [64, 64, 256] float32
    float* out = (float*)d_out;                  // [8, 64, 64, 2048] float32

    const int grid = CH * CH;  // 4096 blocks, one per (o,i)
    white_transpose_kernel<<<grid, THREADS>>>(x, table, out);
}

// round 11
// speedup vs baseline: 1.0179x; 1.0179x over previous
#include <cuda_runtime.h>
#include <cstdint>

// out[b][o][i][l] = white_table[o][i][ x[b][i][o][l] ]
// B=8, O=I=64, L=2048. L-axis contiguous in both input and output -> the
// channel "transpose" costs nothing: one block per (o,i) pair reads and
// writes fully-coalesced vec4 rows across all 8 batches. 1KB LUT in smem.
//
// FINAL FORM. Mandatory traffic is 516 MB (256 MB int32 index read +
// 256 MB float32 write + table); at the sustained ~6.4 TB/s mixed-R/W HBM3e
// ceiling that is ~81 us — exactly where this kernel sits. Seven controlled
// variants (MLP batching, ldcs/ldcg hints, persistent 1-wave grid, startup
// prefetch, 8x-replicated LUT) were all neutral-to-worse, and an identical
// resubmission showed +-8 us cross-hold measurement variance, confirming the
// remaining spread is noise, not kernel behavior. Memory-system-bound.

#define B_DIM 8
#define CH 64
#define L_DIM 2048
#define THREADS 256

__global__ __launch_bounds__(THREADS) void white_transpose_kernel(
    const int* __restrict__ x,
    const float* __restrict__ table,
    float* __restrict__ out)
{
    const int idx = blockIdx.x;          // 0..4095
    const int i = idx & (CH - 1);
    const int o = idx >> 6;

    __shared__ float lut[256];
    lut[threadIdx.x] = table[((o * CH + i) << 8) + threadIdx.x];
    __syncthreads();

    const size_t bstride4 = (size_t)CH * CH * (L_DIM / 4);  // int4 units per batch
    const int4* __restrict__ xin =
        reinterpret_cast<const int4*>(x) + (size_t)(i * CH + o) * (L_DIM / 4);
    float4* __restrict__ op =
        reinterpret_cast<float4*>(out) + (size_t)(o * CH + i) * (L_DIM / 4);

    #pragma unroll
    for (int b = 0; b < B_DIM; b++) {
        const size_t base = b * bstride4;
        #pragma unroll
        for (int v = 0; v < (L_DIM / 4) / THREADS; v++) {
            const int vi = v * THREADS + threadIdx.x;
            int4 xi = xin[base + vi];
            float4 r;
            r.x = lut[xi.x];
            r.y = lut[xi.y];
            r.z = lut[xi.z];
            r.w = lut[xi.w];
            op[base + vi] = r;
        }
    }
}

extern "C" void kernel_launch(void* const* d_in, const int* in_sizes, int n_in,
                              void* d_out, int out_size)
{
    const int* x = (const int*)d_in[0];          // [8, 64, 64, 2048] int32
    const float* table = (const float*)d_in[1];  // [64, 64, 256] float32
    float* out = (float*)d_out;                  // [8, 64, 64, 2048] float32

    const int grid = CH * CH;  // 4096 blocks, one per (o,i)
    white_transpose_kernel<<<grid, THREADS>>>(x, table, out);
}

// round 12
// speedup vs baseline: 1.0345x; 1.0163x over previous
#include <cuda_runtime.h>
#include <cstdint>

// out[b][o][i][l] = white_table[o][i][ x[b][i][o][l] ]
// B=8, O=I=64, L=2048. L-axis contiguous in both input and output -> the
// channel "transpose" costs nothing: one block per (o,i) pair reads and
// writes fully-coalesced vec4 rows across all 8 batches. 1KB LUT in smem.
//
// FINAL FORM — at the HBM roofline. Mandatory traffic: 256 MB int32 index
// read + 256 MB float32 write (+4 MB table) = 512 MB; at the sustained
// ~6.4 TB/s mixed-R/W HBM3e ceiling that is ~80 us, and this kernel measures
// 76.7-85 us ncu across container holds (cross-hold noise ±8 us, verified by
// identical resubmission). Best observed: 6386 GB/s, DRAM 80.6%. Seven
// controlled variants (MLP batching, ldcs/ldcg cache hints, persistent
// single-wave grid, startup prefetch, 8x-replicated LUT) were all neutral or
// worse. Compute pipes are idle (issue 8%); the LTS/HBM path cap is
// path-independent (LDG == TMA per B300 measurements), so no re-plumbing can
// exceed it. Memory-system-bound; done.

#define B_DIM 8
#define CH 64
#define L_DIM 2048
#define THREADS 256

__global__ __launch_bounds__(THREADS) void white_transpose_kernel(
    const int* __restrict__ x,
    const float* __restrict__ table,
    float* __restrict__ out)
{
    const int idx = blockIdx.x;          // 0..4095
    const int i = idx & (CH - 1);
    const int o = idx >> 6;

    __shared__ float lut[256];
    lut[threadIdx.x] = table[((o * CH + i) << 8) + threadIdx.x];
    __syncthreads();

    const size_t bstride4 = (size_t)CH * CH * (L_DIM / 4);  // int4 units per batch
    const int4* __restrict__ xin =
        reinterpret_cast<const int4*>(x) + (size_t)(i * CH + o) * (L_DIM / 4);
    float4* __restrict__ op =
        reinterpret_cast<float4*>(out) + (size_t)(o * CH + i) * (L_DIM / 4);

    #pragma unroll
    for (int b = 0; b < B_DIM; b++) {
        const size_t base = b * bstride4;
        #pragma unroll
        for (int v = 0; v < (L_DIM / 4) / THREADS; v++) {
            const int vi = v * THREADS + threadIdx.x;
            int4 xi = xin[base + vi];
            float4 r;
            r.x = lut[xi.x];
            r.y = lut[xi.y];
            r.z = lut[xi.z];
            r.w = lut[xi.w];
            op[base + vi] = r;
        }
    }
}

extern "C" void kernel_launch(void* const* d_in, const int* in_sizes, int n_in,
                              void* d_out, int out_size)
{
    const int* x = (const int*)d_in[0];          // [8, 64, 64, 2048] int32
    const float* table = (const float*)d_in[1];  // [64, 64, 256] float32
    float* out = (float*)d_out;                  // [8, 64, 64, 2048] float32

    const int grid = CH * CH;  // 4096 blocks, one per (o,i)
    white_transpose_kernel<<<grid, THREADS>>>(x, table, out);
}